// round 2
// baseline (speedup 1.0000x reference)
#include <cuda_runtime.h>
#include <math.h>

#define NQ       12
#define DIM      4096
#define NPATCH   196
#define BATCH    4
#define NROWS    784        // BATCH * NPATCH
#define NGATES   20
#define NPPL     32
#define FEATDIM  2352       // NPATCH * NQ

// ---------------- device scratch (no allocations allowed) ----------------
__device__ float g_feats[NROWS * NQ];
__device__ float g_qkv[3 * NROWS * NQ];
__device__ float g_attn_out[NROWS * NQ];

// Butterfly gate list for n=12 (pidx == gate index; skipped pidx only at tail of last layer)
__constant__ int c_gate_i[NGATES] = {0,2,4,6,8,10,  0,1,4,5,8,9,  0,1,2,3,  0,1,2,3};
__constant__ int c_gate_j[NGATES] = {1,3,5,7,9,11,  2,3,6,7,10,11, 4,5,6,7,  8,9,10,11};

// ---------------- Kernel A: channel-mean + patchify + projection ----------------
__global__ void proj_kernel(const float* __restrict__ x,
                            const float* __restrict__ Wp,
                            const float* __restrict__ bp) {
    int blk = blockIdx.x;                 // 0..783 = b*196 + p
    int b = blk / NPATCH, p = blk % NPATCH;
    int py = p / 14, px = p % 14;
    int j = threadIdx.x;                  // 0..255 patch element
    int r = j >> 4, c = j & 15;
    int h = py * 16 + r, w = px * 16 + c;
    long base = (long)b * 3 * 224 * 224 + (long)h * 224 + w;
    float v = (x[base] + x[base + 224 * 224] + x[base + 2 * 224 * 224]) * (1.0f / 3.0f);

    float acc[NQ];
#pragma unroll
    for (int k = 0; k < NQ; k++) acc[k] = v * Wp[k * 256 + j];

#pragma unroll
    for (int k = 0; k < NQ; k++) {
#pragma unroll
        for (int off = 16; off; off >>= 1)
            acc[k] += __shfl_down_sync(0xffffffffu, acc[k], off);
    }
    __shared__ float sred[8][NQ];
    int warp = j >> 5, lane = j & 31;
    if (lane == 0) {
#pragma unroll
        for (int k = 0; k < NQ; k++) sred[warp][k] = acc[k];
    }
    __syncthreads();
    if (j < NQ) {
        float s = 0.f;
#pragma unroll
        for (int w8 = 0; w8 < 8; w8++) s += sred[w8][j];
        g_feats[blk * NQ + j] = s + bp[j];
    }
}

// ---------------- Kernel B: 12-qubit state evolution + <Z> expvals ----------------
__global__ void __launch_bounds__(256) quantum_kernel(const float* __restrict__ qp,
                                                      const float* __restrict__ kp,
                                                      const float* __restrict__ vp) {
    int row = blockIdx.x;                 // 0..783
    int s   = blockIdx.y;                 // 0..2 (Q/K/V)
    const float* params = (s == 0) ? qp : (s == 1) ? kp : vp;

    __shared__ float st[DIM];
    __shared__ float enc_c[NQ], enc_s[NQ];
    __shared__ float lowprod[16];
    __shared__ float gc2[40], gs2[40], gcs[40];
    __shared__ float red[8][NQ];

    int t = threadIdx.x;                  // 256 threads

    if (t < NQ) {
        float a = 0.5f * g_feats[row * NQ + t];
        float sa, ca; sincosf(a, &sa, &ca);
        enc_c[t] = ca; enc_s[t] = sa;
    }
    if (t < 40) {
        int l = t / NGATES, g = t % NGATES;
        float th = params[l * NPPL + g];  // pidx == g
        float sth, cth; sincosf(th, &sth, &cth);
        gc2[t] = cth * cth; gs2[t] = sth * sth; gcs[t] = cth * sth;
    }
    __syncthreads();

    if (t < 16) {
        float pr = 1.0f;
#pragma unroll
        for (int bpos = 0; bpos < 4; bpos++) {
            int q = 11 - bpos;            // bits 0..3 = qubits 11..8
            pr *= ((t >> bpos) & 1) ? enc_s[q] : enc_c[q];
        }
        lowprod[t] = pr;
    }
    __syncthreads();

    // product state init: idx = t*16 + m; t bits k=0..7 -> state bits k+4 -> qubit 7-k
    float phi = 1.0f;
#pragma unroll
    for (int k = 0; k < 8; k++) {
        int q = 7 - k;
        phi *= ((t >> k) & 1) ? enc_s[q] : enc_c[q];
    }
#pragma unroll
    for (int m = 0; m < 16; m++) st[t * 16 + m] = phi * lowprod[m];
    __syncthreads();

    // 40 RBS gates (2 layers x 20); groups are disjoint per gate
    for (int gg = 0; gg < 40; gg++) {
        int g = (gg >= NGATES) ? gg - NGATES : gg;
        int bi = 11 - c_gate_i[g];        // higher bit
        int bj = 11 - c_gate_j[g];        // lower bit
        float c2 = gc2[gg], s2 = gs2[gg], cs = gcs[gg];
        unsigned mi = 1u << bi, mj = 1u << bj;
#pragma unroll
        for (int k = 0; k < 4; k++) {
            unsigned gid = (unsigned)t + ((unsigned)k << 8);   // 0..1023
            unsigned x1  = ((gid >> bj) << (bj + 1)) | (gid & (mj - 1));
            unsigned idx = ((x1  >> bi) << (bi + 1)) | (x1  & (mi - 1));
            float a00 = st[idx];
            float a01 = st[idx | mj];
            float a10 = st[idx | mi];
            float a11 = st[idx | mi | mj];
            st[idx]           = c2 * a00 + s2 * a01 + cs * (a11 - a10);
            st[idx | mj]      = s2 * a00 + c2 * a01 + cs * (a10 - a11);
            st[idx | mi]      = cs * (a00 - a01) + c2 * a10 + s2 * a11;
            st[idx | mi | mj] = cs * (a01 - a00) + s2 * a10 + c2 * a11;
        }
        __syncthreads();
    }

    // expvals <Z_q> = sum_idx (1-2*bit_q(idx)) * st[idx]^2
    float acc[NQ];
#pragma unroll
    for (int q = 0; q < NQ; q++) acc[q] = 0.f;
#pragma unroll
    for (int m = 0; m < 16; m++) {
        int idx = t * 16 + m;
        float v = st[idx];
        float pr = v * v;
#pragma unroll
        for (int q = 0; q < NQ; q++)
            acc[q] += ((idx >> (11 - q)) & 1) ? -pr : pr;
    }
#pragma unroll
    for (int q = 0; q < NQ; q++) {
#pragma unroll
        for (int off = 16; off; off >>= 1)
            acc[q] += __shfl_down_sync(0xffffffffu, acc[q], off);
    }
    int warp = t >> 5, lane = t & 31;
    if (lane == 0) {
#pragma unroll
        for (int q = 0; q < NQ; q++) red[warp][q] = acc[q];
    }
    __syncthreads();
    if (t < NQ) {
        float sum = 0.f;
#pragma unroll
        for (int w8 = 0; w8 < 8; w8++) sum += red[w8][t];
        g_qkv[((long)s * NROWS + row) * NQ + t] = sum;
    }
}

// ---------------- Kernel C: attention (per-batch) ----------------
__global__ void attn_kernel() {
    int b = blockIdx.x;                   // 0..3
    __shared__ float Ks[NPATCH * NQ];
    __shared__ float Vs[NPATCH * NQ];
    const float* Qg = g_qkv + ((long)0 * NROWS + b * NPATCH) * NQ;
    const float* Kg = g_qkv + ((long)1 * NROWS + b * NPATCH) * NQ;
    const float* Vg = g_qkv + ((long)2 * NROWS + b * NPATCH) * NQ;
    int t = threadIdx.x;
    for (int i = t; i < NPATCH * NQ; i += blockDim.x) {
        Ks[i] = Kg[i];
        Vs[i] = Vg[i];
    }
    __syncthreads();
    if (t < NPATCH) {
        const float scale = 0.28867513459481287f;   // 1/sqrt(12)
        float qv[NQ];
#pragma unroll
        for (int d = 0; d < NQ; d++) qv[d] = Qg[t * NQ + d];
        float m = -1e30f;
        for (int k = 0; k < NPATCH; k++) {
            float sc = 0.f;
#pragma unroll
            for (int d = 0; d < NQ; d++) sc += qv[d] * Ks[k * NQ + d];
            m = fmaxf(m, sc * scale);
        }
        float den = 0.f;
        float o[NQ];
#pragma unroll
        for (int d = 0; d < NQ; d++) o[d] = 0.f;
        for (int k = 0; k < NPATCH; k++) {
            float sc = 0.f;
#pragma unroll
            for (int d = 0; d < NQ; d++) sc += qv[d] * Ks[k * NQ + d];
            float e = __expf(sc * scale - m);
            den += e;
#pragma unroll
            for (int d = 0; d < NQ; d++) o[d] += e * Vs[k * NQ + d];
        }
        float inv = 1.0f / den;
#pragma unroll
        for (int d = 0; d < NQ; d++)
            g_attn_out[(b * NPATCH + t) * NQ + d] = o[d] * inv;
    }
}

// ---------------- Kernel D: classifier ----------------
__global__ void cls_kernel(const float* __restrict__ Wc,
                           const float* __restrict__ bc,
                           float* __restrict__ out) {
    int o = blockIdx.x;                   // 0..999
    int t = threadIdx.x;                  // 128
    const float* W = Wc + (long)o * FEATDIM;
    float a0 = 0.f, a1 = 0.f, a2 = 0.f, a3 = 0.f;
    for (int j = t; j < FEATDIM; j += 128) {
        float w = W[j];
        a0 += w * g_attn_out[j];
        a1 += w * g_attn_out[FEATDIM + j];
        a2 += w * g_attn_out[2 * FEATDIM + j];
        a3 += w * g_attn_out[3 * FEATDIM + j];
    }
#pragma unroll
    for (int off = 16; off; off >>= 1) {
        a0 += __shfl_down_sync(0xffffffffu, a0, off);
        a1 += __shfl_down_sync(0xffffffffu, a1, off);
        a2 += __shfl_down_sync(0xffffffffu, a2, off);
        a3 += __shfl_down_sync(0xffffffffu, a3, off);
    }
    __shared__ float sred[4][4];
    int warp = t >> 5, lane = t & 31;
    if (lane == 0) { sred[warp][0] = a0; sred[warp][1] = a1; sred[warp][2] = a2; sred[warp][3] = a3; }
    __syncthreads();
    if (t == 0) {
        float bias = bc[o];
        float r0 = 0.f, r1 = 0.f, r2 = 0.f, r3 = 0.f;
#pragma unroll
        for (int w4 = 0; w4 < 4; w4++) {
            r0 += sred[w4][0]; r1 += sred[w4][1]; r2 += sred[w4][2]; r3 += sred[w4][3];
        }
        out[0 * 1000 + o] = r0 + bias;
        out[1 * 1000 + o] = r1 + bias;
        out[2 * 1000 + o] = r2 + bias;
        out[3 * 1000 + o] = r3 + bias;
    }
}

// ---------------- launcher ----------------
extern "C" void kernel_launch(void* const* d_in, const int* in_sizes, int n_in,
                              void* d_out, int out_size) {
    const float* x  = (const float*)d_in[0];
    const float* Wp = (const float*)d_in[1];
    const float* bp = (const float*)d_in[2];
    const float* qp = (const float*)d_in[3];
    const float* kp = (const float*)d_in[4];
    const float* vp = (const float*)d_in[5];
    const float* Wc = (const float*)d_in[6];
    const float* bc = (const float*)d_in[7];
    float* out = (float*)d_out;

    proj_kernel<<<NROWS, 256>>>(x, Wp, bp);
    dim3 gq(NROWS, 3);
    quantum_kernel<<<gq, 256>>>(qp, kp, vp);
    attn_kernel<<<BATCH, 224>>>();
    cls_kernel<<<1000, 128>>>(Wc, bc, out);
}

// round 4
// speedup vs baseline: 2.0682x; 2.0682x over previous
#include <cuda_runtime.h>
#include <math.h>

#define NQ       12
#define NPATCH   196
#define BATCH    4
#define NROWS    784        // BATCH * NPATCH
#define FEATDIM  2352       // NPATCH * NQ
#define FULLMASK 0xffffffffu

// ---------------- device scratch (no allocations allowed) ----------------
__device__ float g_feats[NROWS * NQ];
__device__ float g_qkv[3 * NROWS * NQ];
__device__ float g_attn_out[NROWS * NQ];
__device__ float g_gcoef[3][80];      // per s: 40 gates x (0.5*cos2t, 0.5*sin2t)

// ---------------- Kernel A: channel-mean + patchify + projection ----------------
__global__ void proj_kernel(const float* __restrict__ x,
                            const float* __restrict__ Wp,
                            const float* __restrict__ bp) {
    int blk = blockIdx.x;                 // 0..783 = b*196 + p
    int b = blk / NPATCH, p = blk % NPATCH;
    int py = p / 14, px = p % 14;
    int j = threadIdx.x;                  // 0..255 patch element
    int r = j >> 4, c = j & 15;
    int h = py * 16 + r, w = px * 16 + c;
    long base = (long)b * 3 * 224 * 224 + (long)h * 224 + w;
    float v = (x[base] + x[base + 224 * 224] + x[base + 2 * 224 * 224]) * (1.0f / 3.0f);

    float acc[NQ];
#pragma unroll
    for (int k = 0; k < NQ; k++) acc[k] = v * Wp[k * 256 + j];

#pragma unroll
    for (int k = 0; k < NQ; k++) {
#pragma unroll
        for (int off = 16; off; off >>= 1)
            acc[k] += __shfl_down_sync(FULLMASK, acc[k], off);
    }
    __shared__ float sred[8][NQ];
    int warp = j >> 5, lane = j & 31;
    if (lane == 0) {
#pragma unroll
        for (int k = 0; k < NQ; k++) sred[warp][k] = acc[k];
    }
    __syncthreads();
    if (j < NQ) {
        float s = 0.f;
#pragma unroll
        for (int w8 = 0; w8 < 8; w8++) s += sred[w8][j];
        g_feats[blk * NQ + j] = s + bp[j];
    }
}

// ---------------- coefficient prep: 0.5*cos(2t), 0.5*sin(2t) per gate ----------------
__global__ void coef_kernel(const float* __restrict__ qp,
                            const float* __restrict__ kp,
                            const float* __restrict__ vp) {
    int t = threadIdx.x;                  // need 120
    if (t < 120) {
        int s = t / 40, gg = t % 40;
        const float* pp = (s == 0) ? qp : (s == 1) ? kp : vp;
        int l = gg / 20, g = gg % 20;
        float th = pp[l * 32 + g];        // pidx == gate index within layer
        float s2, c2; sincosf(2.0f * th, &s2, &c2);
        g_gcoef[s][2 * gg + 0] = 0.5f * c2;
        g_gcoef[s][2 * gg + 1] = 0.5f * s2;
    }
}

// ---------------- quantum gate primitives (warp-register state) ----------------
// Amplitude index: idx = (lane << 7) | r.  lane bit b = amp bit 7+b, reg bit m = amp bit m.
// RBS on amp bits (p1>p2): with u=e00+e01, v=e00-e01, p=e10+e11, q=e10-e11,
// v' = c2t*v - s2t*q, q' = s2t*v + c2t*q, outs = (u±v')/2, (p±q')/2.
// ch = 0.5*cos2t, sh = 0.5*sin2t everywhere below.

template<int MH, int ML>
__device__ __forceinline__ void gateR(float* a, float ch, float sh) {
#pragma unroll
    for (int r = 0; r < 128; r++) {
        if ((r & (MH | ML)) == 0) {
            float e00 = a[r], e01 = a[r | ML], e10 = a[r | MH], e11 = a[r | MH | ML];
            float u = e00 + e01, v = e00 - e01;
            float p = e10 + e11, q = e10 - e11;
            float hv = ch * v - sh * q;
            float hq = sh * v + ch * q;
            float uh = 0.5f * u, ph = 0.5f * p;
            a[r]           = uh + hv;
            a[r | ML]      = uh - hv;
            a[r | MH]      = ph + hq;
            a[r | MH | ML] = ph - hq;
        }
    }
}

// p1 in lane (LBIT = p1-7), p2 in regs (mask ML)
template<int LBIT, int ML>
__device__ __forceinline__ void gateM(float* a, float ch, float sh, int lane) {
    const unsigned msk = 1u << LBIT;
    float sgnsh = (lane & msk) ? sh : -sh;
#pragma unroll
    for (int r = 0; r < 128; r++) {
        if ((r & ML) == 0) {
            float s = a[r] + a[r | ML];
            float d = a[r] - a[r | ML];        // v on lane-bit=0, q on lane-bit=1
            float od = __shfl_xor_sync(FULLMASK, d, msk);
            float h = ch * d + sgnsh * od;     // hv or hq
            float sh2 = 0.5f * s;
            a[r]      = sh2 + h;
            a[r | ML] = sh2 - h;
        }
    }
}

// both bits in lane: LB1 = p1-7 > LB2 = p2-7
template<int LB1, int LB2>
__device__ __forceinline__ void gateL(float* a, float ch, float sh, int lane) {
    const unsigned m1 = 1u << LB1, m2 = 1u << LB2;
    const bool b1 = (lane & m1) != 0, b2 = (lane & m2) != 0;
    const float sgn2 = b2 ? -1.0f : 1.0f;
    const float cA2 = b2 ? ch : 1.0f;
    const float cB2 = b2 ? (b1 ? sh : -sh) : 0.0f;
    const float cA3 = b2 ? -1.0f : 0.5f;
    const float cB3 = b2 ? 0.5f : 1.0f;
#pragma unroll
    for (int r = 0; r < 128; r++) {
        float e = a[r];
        float o = __shfl_xor_sync(FULLMASK, e, m2);
        float x = o + sgn2 * e;                      // u/p on b2=0, v/q on b2=1
        float o2 = __shfl_xor_sync(FULLMASK, x, m1);
        x = cA2 * x + cB2 * o2;                      // rotate (halved) on b2=1
        float o3 = __shfl_xor_sync(FULLMASK, x, m2);
        a[r] = cA3 * x + cB3 * o3;                   // reconstruct
    }
}

// ---------------- Kernel B: warp-per-state quantum evolution ----------------
__global__ void __launch_bounds__(128, 2) quantum_kernel() {
    int warp = threadIdx.x >> 5, lane = threadIdx.x & 31;
    int unit = blockIdx.x * 4 + warp;       // 0..2351
    int row = unit % NROWS;
    int s = unit / NROWS;                   // 0..2

    __shared__ float shco[4][80];
    {
        const float* gc = g_gcoef[s];
        for (int i = lane; i < 80; i += 32) shco[warp][i] = gc[i];
        __syncwarp();
    }
    const float* co = shco[warp];

    // angle encoding: lane q<12 computes cos/sin(x_q/2), broadcast via shfl
    float ang = (lane < NQ) ? 0.5f * g_feats[row * NQ + lane] : 0.0f;
    float cv, sv; sincosf(ang, &sv, &cv);

    // phi = product over lane bits b (amp bit 7+b -> qubit 4-b)
    float phi = 1.0f;
#pragma unroll
    for (int b = 0; b < 5; b++) {
        float cb = __shfl_sync(FULLMASK, cv, 4 - b);
        float sb = __shfl_sync(FULLMASK, sv, 4 - b);
        phi *= ((lane >> b) & 1) ? sb : cb;
    }

    float a[128];
    a[0] = phi;
#pragma unroll
    for (int m = 0; m < 7; m++) {           // reg bit m -> qubit 11-m
        float cm = __shfl_sync(FULLMASK, cv, 11 - m);
        float sm = __shfl_sync(FULLMASK, sv, 11 - m);
        int len = 1 << m;
#pragma unroll
        for (int i = 0; i < 128; i++) {
            if (i < len) {
                a[i + len] = a[i] * sm;
                a[i] *= cm;
            }
        }
    }

    // 2 layers x 20 gates (amp-bit pairs fixed at compile time)
#pragma unroll
    for (int l = 0; l < 2; l++) {
        const float* c = co + l * 40;
        gateL<4, 3>(a, c[0],  c[1],  lane);   // (11,10)
        gateL<2, 1>(a, c[2],  c[3],  lane);   // (9,8)
        gateM<0, 64>(a, c[4],  c[5],  lane);  // (7,6)
        gateR<32, 16>(a, c[6],  c[7]);        // (5,4)
        gateR<8, 4>(a, c[8],  c[9]);          // (3,2)
        gateR<2, 1>(a, c[10], c[11]);         // (1,0)
        gateL<4, 2>(a, c[12], c[13], lane);   // (11,9)
        gateL<3, 1>(a, c[14], c[15], lane);   // (10,8)
        gateM<0, 32>(a, c[16], c[17], lane);  // (7,5)
        gateR<64, 16>(a, c[18], c[19]);       // (6,4)
        gateR<8, 2>(a, c[20], c[21]);         // (3,1)
        gateR<4, 1>(a, c[22], c[23]);         // (2,0)
        gateL<4, 0>(a, c[24], c[25], lane);   // (11,7)
        gateM<3, 64>(a, c[26], c[27], lane);  // (10,6)
        gateM<2, 32>(a, c[28], c[29], lane);  // (9,5)
        gateM<1, 16>(a, c[30], c[31], lane);  // (8,4)
        gateM<4, 8>(a, c[32], c[33], lane);   // (11,3)
        gateM<3, 4>(a, c[34], c[35], lane);   // (10,2)
        gateM<2, 2>(a, c[36], c[37], lane);   // (9,1)
        gateM<1, 1>(a, c[38], c[39], lane);   // (8,0)
    }

    // expvals: squares, then fold reg bits computing per-bit signed sums
#pragma unroll
    for (int r = 0; r < 128; r++) a[r] *= a[r];

    float D[7];
#pragma unroll
    for (int m = 0; m < 7; m++) {
        int half = 128 >> (m + 1);
        float dsum = 0.0f;
#pragma unroll
        for (int i = 0; i < 64; i++) {
            if (i < half) {
                float lo = a[2 * i], hi = a[2 * i + 1];
                dsum += lo - hi;
                a[i] = lo + hi;
            }
        }
        D[m] = dsum;                        // partial <Z_{11-m}> for this lane
    }
    float S = a[0];                          // per-lane total prob

    // reduce D over all lanes (butterfly)
#pragma unroll
    for (int m = 0; m < 7; m++) {
#pragma unroll
        for (int b = 0; b < 5; b++)
            D[m] += __shfl_xor_sync(FULLMASK, D[m], 1 << b);
    }

    // lane-bit qubits: signed reductions of S
    float L[5];
#pragma unroll
    for (int b = 0; b < 5; b++) {
        float o = __shfl_xor_sync(FULLMASK, S, 1 << b);
        L[b] = (lane & (1 << b)) ? (o - S) : (S - o);
        S += o;
    }
#pragma unroll
    for (int b = 0; b < 5; b++) {
#pragma unroll
        for (int b2 = b + 1; b2 < 5; b2++)
            L[b] += __shfl_xor_sync(FULLMASK, L[b], 1 << b2);
    }

    if (lane == 0) {
        float* dst = g_qkv + ((long)s * NROWS + row) * NQ;
        dst[11] = D[0]; dst[10] = D[1]; dst[9] = D[2]; dst[8] = D[3];
        dst[7]  = D[4]; dst[6]  = D[5]; dst[5] = D[6];
        dst[4]  = L[0]; dst[3]  = L[1]; dst[2] = L[2]; dst[1] = L[3]; dst[0] = L[4];
    }
}

// ---------------- Kernel C: attention (per-batch) ----------------
__global__ void attn_kernel() {
    int b = blockIdx.x;                   // 0..3
    __shared__ float Ks[NPATCH * NQ];
    __shared__ float Vs[NPATCH * NQ];
    const float* Qg = g_qkv + ((long)0 * NROWS + b * NPATCH) * NQ;
    const float* Kg = g_qkv + ((long)1 * NROWS + b * NPATCH) * NQ;
    const float* Vg = g_qkv + ((long)2 * NROWS + b * NPATCH) * NQ;
    int t = threadIdx.x;
    for (int i = t; i < NPATCH * NQ; i += blockDim.x) {
        Ks[i] = Kg[i];
        Vs[i] = Vg[i];
    }
    __syncthreads();
    if (t < NPATCH) {
        const float scale = 0.28867513459481287f;   // 1/sqrt(12)
        float qv[NQ];
#pragma unroll
        for (int d = 0; d < NQ; d++) qv[d] = Qg[t * NQ + d];
        float m = -1e30f;
        for (int k = 0; k < NPATCH; k++) {
            float sc = 0.f;
#pragma unroll
            for (int d = 0; d < NQ; d++) sc += qv[d] * Ks[k * NQ + d];
            m = fmaxf(m, sc * scale);
        }
        float den = 0.f;
        float o[NQ];
#pragma unroll
        for (int d = 0; d < NQ; d++) o[d] = 0.f;
        for (int k = 0; k < NPATCH; k++) {
            float sc = 0.f;
#pragma unroll
            for (int d = 0; d < NQ; d++) sc += qv[d] * Ks[k * NQ + d];
            float e = __expf(sc * scale - m);
            den += e;
#pragma unroll
            for (int d = 0; d < NQ; d++) o[d] += e * Vs[k * NQ + d];
        }
        float inv = 1.0f / den;
#pragma unroll
        for (int d = 0; d < NQ; d++)
            g_attn_out[(b * NPATCH + t) * NQ + d] = o[d] * inv;
    }
}

// ---------------- Kernel D: classifier (float4) ----------------
__global__ void cls_kernel(const float* __restrict__ Wc,
                           const float* __restrict__ bc,
                           float* __restrict__ out) {
    int o = blockIdx.x;                   // 0..999
    int t = threadIdx.x;                  // 256
    const float4* W4 = (const float4*)(Wc + (long)o * FEATDIM);
    const float4* A4 = (const float4*)g_attn_out;   // [4][588] float4
    float a0 = 0.f, a1 = 0.f, a2 = 0.f, a3 = 0.f;
    const int NF4 = FEATDIM / 4;          // 588
    for (int j = t; j < NF4; j += 256) {
        float4 w = W4[j];
        float4 x0 = A4[j];
        float4 x1 = A4[NF4 + j];
        float4 x2 = A4[2 * NF4 + j];
        float4 x3 = A4[3 * NF4 + j];
        a0 += w.x * x0.x + w.y * x0.y + w.z * x0.z + w.w * x0.w;
        a1 += w.x * x1.x + w.y * x1.y + w.z * x1.z + w.w * x1.w;
        a2 += w.x * x2.x + w.y * x2.y + w.z * x2.z + w.w * x2.w;
        a3 += w.x * x3.x + w.y * x3.y + w.z * x3.z + w.w * x3.w;
    }
#pragma unroll
    for (int off = 16; off; off >>= 1) {
        a0 += __shfl_down_sync(FULLMASK, a0, off);
        a1 += __shfl_down_sync(FULLMASK, a1, off);
        a2 += __shfl_down_sync(FULLMASK, a2, off);
        a3 += __shfl_down_sync(FULLMASK, a3, off);
    }
    __shared__ float sred[8][4];
    int warp = t >> 5, lane = t & 31;
    if (lane == 0) { sred[warp][0] = a0; sred[warp][1] = a1; sred[warp][2] = a2; sred[warp][3] = a3; }
    __syncthreads();
    if (t == 0) {
        float bias = bc[o];
        float r0 = 0.f, r1 = 0.f, r2 = 0.f, r3 = 0.f;
#pragma unroll
        for (int w8 = 0; w8 < 8; w8++) {
            r0 += sred[w8][0]; r1 += sred[w8][1]; r2 += sred[w8][2]; r3 += sred[w8][3];
        }
        out[0 * 1000 + o] = r0 + bias;
        out[1 * 1000 + o] = r1 + bias;
        out[2 * 1000 + o] = r2 + bias;
        out[3 * 1000 + o] = r3 + bias;
    }
}

// ---------------- launcher ----------------
extern "C" void kernel_launch(void* const* d_in, const int* in_sizes, int n_in,
                              void* d_out, int out_size) {
    const float* x  = (const float*)d_in[0];
    const float* Wp = (const float*)d_in[1];
    const float* bp = (const float*)d_in[2];
    const float* qp = (const float*)d_in[3];
    const float* kp = (const float*)d_in[4];
    const float* vp = (const float*)d_in[5];
    const float* Wc = (const float*)d_in[6];
    const float* bc = (const float*)d_in[7];
    float* out = (float*)d_out;

    proj_kernel<<<NROWS, 256>>>(x, Wp, bp);
    coef_kernel<<<1, 128>>>(qp, kp, vp);
    quantum_kernel<<<588, 128>>>();
    attn_kernel<<<BATCH, 224>>>();
    cls_kernel<<<1000, 256>>>(Wc, bc, out);
}

// round 5
// speedup vs baseline: 2.5913x; 1.2529x over previous
#include <cuda_runtime.h>
#include <math.h>

#define NQ       12
#define NPATCH   196
#define BATCH    4
#define NROWS    784        // BATCH * NPATCH
#define FEATDIM  2352       // NPATCH * NQ
#define FULLMASK 0xffffffffu

// ---------------- device scratch (no allocations allowed) ----------------
__device__ float g_feats[NROWS * NQ];
__device__ float g_qkv[3 * NROWS * NQ];
__device__ float g_attn_out[NROWS * NQ];
__device__ float g_gcoef[3][80];      // per s: 40 gates x (0.5*cos2t, 0.5*sin2t)

// ---------------- Kernel A: channel-mean + patchify + projection ----------------
__global__ void proj_kernel(const float* __restrict__ x,
                            const float* __restrict__ Wp,
                            const float* __restrict__ bp) {
    int blk = blockIdx.x;                 // 0..783 = b*196 + p
    int b = blk / NPATCH, p = blk % NPATCH;
    int py = p / 14, px = p % 14;
    int j = threadIdx.x;                  // 0..255 patch element
    int r = j >> 4, c = j & 15;
    int h = py * 16 + r, w = px * 16 + c;
    long base = (long)b * 3 * 224 * 224 + (long)h * 224 + w;
    float v = (x[base] + x[base + 224 * 224] + x[base + 2 * 224 * 224]) * (1.0f / 3.0f);

    float acc[NQ];
#pragma unroll
    for (int k = 0; k < NQ; k++) acc[k] = v * Wp[k * 256 + j];

#pragma unroll
    for (int k = 0; k < NQ; k++) {
#pragma unroll
        for (int off = 16; off; off >>= 1)
            acc[k] += __shfl_down_sync(FULLMASK, acc[k], off);
    }
    __shared__ float sred[8][NQ];
    int warp = j >> 5, lane = j & 31;
    if (lane == 0) {
#pragma unroll
        for (int k = 0; k < NQ; k++) sred[warp][k] = acc[k];
    }
    __syncthreads();
    if (j < NQ) {
        float s = 0.f;
#pragma unroll
        for (int w8 = 0; w8 < 8; w8++) s += sred[w8][j];
        g_feats[blk * NQ + j] = s + bp[j];
    }
}

// ---------------- coefficient prep: 0.5*cos(2t), 0.5*sin(2t) per gate ----------------
__global__ void coef_kernel(const float* __restrict__ qp,
                            const float* __restrict__ kp,
                            const float* __restrict__ vp) {
    int t = threadIdx.x;                  // need 120
    if (t < 120) {
        int s = t / 40, gg = t % 40;
        const float* pp = (s == 0) ? qp : (s == 1) ? kp : vp;
        int l = gg / 20, g = gg % 20;
        float th = pp[l * 32 + g];        // pidx == gate index within layer
        float s2, c2; sincosf(2.0f * th, &s2, &c2);
        g_gcoef[s][2 * gg + 0] = 0.5f * c2;
        g_gcoef[s][2 * gg + 1] = 0.5f * s2;
    }
}

// ---------------- quantum gate primitives (warp-register state) ----------------
// Mapping: amp bit <-> storage:
//   lane bit 0..4  <-> amp bits {1, 2, 5, 6, 11}  <-> qubits {10, 9, 6, 5, 0}
//   reg  bit 0..6  <-> amp bits {0, 3, 4, 7, 8, 9, 10} <-> qubits {11, 8, 7, 4, 3, 2, 1}
// ch = 0.5*cos2t, sh = 0.5*sin2t everywhere.

// both amp bits in regs (MH = w1-bit mask > role; ML = w2-bit mask)
template<int MH, int ML>
__device__ __forceinline__ void gateR(float* a, float ch, float sh) {
#pragma unroll
    for (int r = 0; r < 128; r++) {
        if ((r & (MH | ML)) == 0) {
            float e00 = a[r], e01 = a[r | ML], e10 = a[r | MH], e11 = a[r | MH | ML];
            float u = e00 + e01, v = e00 - e01;
            float p = e10 + e11, q = e10 - e11;
            float hv = ch * v - sh * q;
            float hq = sh * v + ch * q;
            float uh = 0.5f * u, ph = 0.5f * p;
            a[r]           = uh + hv;
            a[r | ML]      = uh - hv;
            a[r | MH]      = ph + hq;
            a[r | MH | ML] = ph - hq;
        }
    }
}

// w1-bit in lane (LBIT), w2-bit in regs (ML)
template<int LBIT, int ML>
__device__ __forceinline__ void gateM(float* a, float ch, float sh, int lane) {
    const unsigned msk = 1u << LBIT;
    float sgnsh = (lane & msk) ? sh : -sh;
#pragma unroll
    for (int r = 0; r < 128; r++) {
        if ((r & ML) == 0) {
            float s = a[r] + a[r | ML];
            float d = a[r] - a[r | ML];        // v on lane-bit=0, q on lane-bit=1
            float od = __shfl_xor_sync(FULLMASK, d, msk);
            float h = ch * d + sgnsh * od;     // hv or hq
            float sh2 = 0.5f * s;
            a[r]      = sh2 + h;
            a[r | ML] = sh2 - h;
        }
    }
}

// w2-bit in lane (LBIT), w1-bit in regs (MH). Branch-free: lane-side signs cancel.
template<int LBIT, int MH>
__device__ __forceinline__ void gateMlo(float* a, float ch, float sh, int lane) {
    const unsigned msk = 1u << LBIT;
#pragma unroll
    for (int r = 0; r < 128; r++) {
        if ((r & MH) == 0) {
            float x0 = a[r], x1 = a[r | MH];
            float y0 = __shfl_xor_sync(FULLMASK, x0, msk);
            float y1 = __shfl_xor_sync(FULLMASK, x1, msk);
            float dx = x0 - y0, dq = x1 - y1;
            float uh = 0.5f * (x0 + y0);
            float ph = 0.5f * (x1 + y1);
            a[r]      = uh + ch * dx - sh * dq;
            a[r | MH] = ph + sh * dx + ch * dq;
        }
    }
}

// ---------------- Kernel B: warp-per-state quantum evolution ----------------
__global__ void __launch_bounds__(128, 2) quantum_kernel() {
    int warp = threadIdx.x >> 5, lane = threadIdx.x & 31;
    int unit = blockIdx.x * 4 + warp;       // 0..2351
    int row = unit % NROWS;
    int s = unit / NROWS;                   // 0..2

    __shared__ float shco[4][80];
    {
        const float* gc = g_gcoef[s];
        for (int i = lane; i < 80; i += 32) shco[warp][i] = gc[i];
        __syncwarp();
    }
    const float* co = shco[warp];

    // angle encoding: lane q<12 computes cos/sin(x_q/2), broadcast via shfl
    float ang = (lane < NQ) ? 0.5f * g_feats[row * NQ + lane] : 0.0f;
    float cv, sv; sincosf(ang, &sv, &cv);

    // phi over lane bits: lane bit b -> qubit {10,9,6,5,0}
    float phi = 1.0f;
    {
        float cb, sb;
        cb = __shfl_sync(FULLMASK, cv, 10); sb = __shfl_sync(FULLMASK, sv, 10);
        phi *= (lane & 1)  ? sb : cb;
        cb = __shfl_sync(FULLMASK, cv, 9);  sb = __shfl_sync(FULLMASK, sv, 9);
        phi *= (lane & 2)  ? sb : cb;
        cb = __shfl_sync(FULLMASK, cv, 6);  sb = __shfl_sync(FULLMASK, sv, 6);
        phi *= (lane & 4)  ? sb : cb;
        cb = __shfl_sync(FULLMASK, cv, 5);  sb = __shfl_sync(FULLMASK, sv, 5);
        phi *= (lane & 8)  ? sb : cb;
        cb = __shfl_sync(FULLMASK, cv, 0);  sb = __shfl_sync(FULLMASK, sv, 0);
        phi *= (lane & 16) ? sb : cb;
    }

    // product-state init over reg bits: reg bit m -> qubit {11,8,7,4,3,2,1}
    const int rq[7] = {11, 8, 7, 4, 3, 2, 1};
    float a[128];
    a[0] = phi;
#pragma unroll
    for (int m = 0; m < 7; m++) {
        float cm = __shfl_sync(FULLMASK, cv, rq[m]);
        float sm = __shfl_sync(FULLMASK, sv, rq[m]);
        int len = 1 << m;
#pragma unroll
        for (int i = 0; i < 128; i++) {
            if (i < len) {
                a[i + len] = a[i] * sm;
                a[i] *= cm;
            }
        }
    }

    // 2 layers x 20 gates; no gateL in this mapping
#pragma unroll 1
    for (int l = 0; l < 2; l++) {
        const float* c = co + l * 40;
        gateM  <4, 64>(a, c[0],  c[1],  lane);   // (q0,q1)   amp(11,10)
        gateR  <32, 16>(a, c[2],  c[3]);         // (q2,q3)   amp(9,8)
        gateMlo<3, 8>(a, c[4],  c[5],  lane);    // (q4,q5)   amp(7,6)
        gateM  <2, 4>(a, c[6],  c[7],  lane);    // (q6,q7)   amp(5,4)
        gateMlo<1, 2>(a, c[8],  c[9],  lane);    // (q8,q9)   amp(3,2)
        gateM  <0, 1>(a, c[10], c[11], lane);    // (q10,q11) amp(1,0)
        gateM  <4, 32>(a, c[12], c[13], lane);   // (q0,q2)   amp(11,9)
        gateR  <64, 16>(a, c[14], c[15]);        // (q1,q3)   amp(10,8)
        gateMlo<2, 8>(a, c[16], c[17], lane);    // (q4,q6)   amp(7,5)
        gateM  <3, 4>(a, c[18], c[19], lane);    // (q5,q7)   amp(6,4)
        gateMlo<0, 2>(a, c[20], c[21], lane);    // (q8,q10)  amp(3,1)
        gateM  <1, 1>(a, c[22], c[23], lane);    // (q9,q11)  amp(2,0)
        gateM  <4, 8>(a, c[24], c[25], lane);    // (q0,q4)   amp(11,7)
        gateMlo<3, 64>(a, c[26], c[27], lane);   // (q1,q5)   amp(10,6)
        gateMlo<2, 32>(a, c[28], c[29], lane);   // (q2,q6)   amp(9,5)
        gateR  <16, 4>(a, c[30], c[31]);         // (q3,q7)   amp(8,4)
        gateM  <4, 2>(a, c[32], c[33], lane);    // (q0,q8)   amp(11,3)
        gateMlo<1, 64>(a, c[34], c[35], lane);   // (q1,q9)   amp(10,2)
        gateMlo<0, 32>(a, c[36], c[37], lane);   // (q2,q10)  amp(9,1)
        gateR  <16, 1>(a, c[38], c[39]);         // (q3,q11)  amp(8,0)
    }

    // expvals: squares, then fold reg bits computing per-bit signed sums
#pragma unroll
    for (int r = 0; r < 128; r++) a[r] *= a[r];

    float D[7];
#pragma unroll
    for (int m = 0; m < 7; m++) {
        int half = 128 >> (m + 1);
        float dsum = 0.0f;
#pragma unroll
        for (int i = 0; i < 64; i++) {
            if (i < half) {
                float lo = a[2 * i], hi = a[2 * i + 1];
                dsum += lo - hi;
                a[i] = lo + hi;
            }
        }
        D[m] = dsum;                        // partial <Z_{rq[m]}> for this lane
    }
    float S = a[0];                          // per-lane total prob

    // reduce D over all lanes (butterfly)
#pragma unroll
    for (int m = 0; m < 7; m++) {
#pragma unroll
        for (int b = 0; b < 5; b++)
            D[m] += __shfl_xor_sync(FULLMASK, D[m], 1 << b);
    }

    // lane-bit qubits: signed reductions of S
    float L[5];
#pragma unroll
    for (int b = 0; b < 5; b++) {
        float o = __shfl_xor_sync(FULLMASK, S, 1 << b);
        L[b] = (lane & (1 << b)) ? (o - S) : (S - o);
        S += o;
    }
#pragma unroll
    for (int b = 0; b < 5; b++) {
#pragma unroll
        for (int b2 = b + 1; b2 < 5; b2++)
            L[b] += __shfl_xor_sync(FULLMASK, L[b], 1 << b2);
    }

    if (lane == 0) {
        float* dst = g_qkv + ((long)s * NROWS + row) * NQ;
        // D[m] -> qubit rq[m] = {11,8,7,4,3,2,1}; L[b] -> qubit {10,9,6,5,0}
        dst[11] = D[0]; dst[8] = D[1]; dst[7] = D[2]; dst[4] = D[3];
        dst[3]  = D[4]; dst[2] = D[5]; dst[1] = D[6];
        dst[10] = L[0]; dst[9] = L[1]; dst[6] = L[2]; dst[5] = L[3]; dst[0] = L[4];
    }
}

// ---------------- Kernel C: attention, warp per query row ----------------
__global__ void attn_kernel() {
    int gw = blockIdx.x * 4 + (threadIdx.x >> 5);    // 0..783
    int lane = threadIdx.x & 31;
    int b = gw / NPATCH, q = gw % NPATCH;
    const float scale = 0.28867513459481287f;        // 1/sqrt(12)

    const float* Qr = g_qkv + ((long)0 * NROWS + b * NPATCH + q) * NQ;
    const float* Kb = g_qkv + ((long)1 * NROWS + b * NPATCH) * NQ;
    const float* Vb = g_qkv + ((long)2 * NROWS + b * NPATCH) * NQ;

    float4 q0 = *(const float4*)(Qr);
    float4 q1 = *(const float4*)(Qr + 4);
    float4 q2 = *(const float4*)(Qr + 8);

    float sc[7];
    float m = -1e30f;
#pragma unroll
    for (int i = 0; i < 7; i++) {
        int k = lane + 32 * i;
        float v = -1e30f;
        if (k < NPATCH) {
            const float* Kr = Kb + k * NQ;
            float4 k0 = *(const float4*)Kr;
            float4 k1 = *(const float4*)(Kr + 4);
            float4 k2 = *(const float4*)(Kr + 8);
            v = q0.x * k0.x + q0.y * k0.y + q0.z * k0.z + q0.w * k0.w
              + q1.x * k1.x + q1.y * k1.y + q1.z * k1.z + q1.w * k1.w
              + q2.x * k2.x + q2.y * k2.y + q2.z * k2.z + q2.w * k2.w;
            v *= scale;
        }
        sc[i] = v;
        m = fmaxf(m, v);
    }
#pragma unroll
    for (int off = 16; off; off >>= 1)
        m = fmaxf(m, __shfl_xor_sync(FULLMASK, m, off));

    float den = 0.f;
    float o[NQ];
#pragma unroll
    for (int d = 0; d < NQ; d++) o[d] = 0.f;
#pragma unroll
    for (int i = 0; i < 7; i++) {
        int k = lane + 32 * i;
        if (k < NPATCH) {
            float e = __expf(sc[i] - m);
            den += e;
            const float* Vr = Vb + k * NQ;
            float4 v0 = *(const float4*)Vr;
            float4 v1 = *(const float4*)(Vr + 4);
            float4 v2 = *(const float4*)(Vr + 8);
            o[0] += e * v0.x; o[1] += e * v0.y; o[2]  += e * v0.z; o[3]  += e * v0.w;
            o[4] += e * v1.x; o[5] += e * v1.y; o[6]  += e * v1.z; o[7]  += e * v1.w;
            o[8] += e * v2.x; o[9] += e * v2.y; o[10] += e * v2.z; o[11] += e * v2.w;
        }
    }
#pragma unroll
    for (int off = 16; off; off >>= 1) {
        den += __shfl_xor_sync(FULLMASK, den, off);
#pragma unroll
        for (int d = 0; d < NQ; d++)
            o[d] += __shfl_xor_sync(FULLMASK, o[d], off);
    }
    if (lane == 0) {
        float inv = 1.0f / den;
        float* dst = g_attn_out + ((long)b * NPATCH + q) * NQ;
#pragma unroll
        for (int d = 0; d < NQ; d++) dst[d] = o[d] * inv;
    }
}

// ---------------- Kernel D: classifier (float4) ----------------
__global__ void cls_kernel(const float* __restrict__ Wc,
                           const float* __restrict__ bc,
                           float* __restrict__ out) {
    int o = blockIdx.x;                   // 0..999
    int t = threadIdx.x;                  // 256
    const float4* W4 = (const float4*)(Wc + (long)o * FEATDIM);
    const float4* A4 = (const float4*)g_attn_out;   // [4][588] float4
    float a0 = 0.f, a1 = 0.f, a2 = 0.f, a3 = 0.f;
    const int NF4 = FEATDIM / 4;          // 588
    for (int j = t; j < NF4; j += 256) {
        float4 w = W4[j];
        float4 x0 = A4[j];
        float4 x1 = A4[NF4 + j];
        float4 x2 = A4[2 * NF4 + j];
        float4 x3 = A4[3 * NF4 + j];
        a0 += w.x * x0.x + w.y * x0.y + w.z * x0.z + w.w * x0.w;
        a1 += w.x * x1.x + w.y * x1.y + w.z * x1.z + w.w * x1.w;
        a2 += w.x * x2.x + w.y * x2.y + w.z * x2.z + w.w * x2.w;
        a3 += w.x * x3.x + w.y * x3.y + w.z * x3.z + w.w * x3.w;
    }
#pragma unroll
    for (int off = 16; off; off >>= 1) {
        a0 += __shfl_down_sync(FULLMASK, a0, off);
        a1 += __shfl_down_sync(FULLMASK, a1, off);
        a2 += __shfl_down_sync(FULLMASK, a2, off);
        a3 += __shfl_down_sync(FULLMASK, a3, off);
    }
    __shared__ float sred[8][4];
    int warp = t >> 5, lane = t & 31;
    if (lane == 0) { sred[warp][0] = a0; sred[warp][1] = a1; sred[warp][2] = a2; sred[warp][3] = a3; }
    __syncthreads();
    if (t == 0) {
        float bias = bc[o];
        float r0 = 0.f, r1 = 0.f, r2 = 0.f, r3 = 0.f;
#pragma unroll
        for (int w8 = 0; w8 < 8; w8++) {
            r0 += sred[w8][0]; r1 += sred[w8][1]; r2 += sred[w8][2]; r3 += sred[w8][3];
        }
        out[0 * 1000 + o] = r0 + bias;
        out[1 * 1000 + o] = r1 + bias;
        out[2 * 1000 + o] = r2 + bias;
        out[3 * 1000 + o] = r3 + bias;
    }
}

// ---------------- launcher ----------------
extern "C" void kernel_launch(void* const* d_in, const int* in_sizes, int n_in,
                              void* d_out, int out_size) {
    const float* x  = (const float*)d_in[0];
    const float* Wp = (const float*)d_in[1];
    const float* bp = (const float*)d_in[2];
    const float* qp = (const float*)d_in[3];
    const float* kp = (const float*)d_in[4];
    const float* vp = (const float*)d_in[5];
    const float* Wc = (const float*)d_in[6];
    const float* bc = (const float*)d_in[7];
    float* out = (float*)d_out;

    coef_kernel<<<1, 128>>>(qp, kp, vp);
    proj_kernel<<<NROWS, 256>>>(x, Wp, bp);
    quantum_kernel<<<588, 128>>>();
    attn_kernel<<<196, 128>>>();
    cls_kernel<<<1000, 256>>>(Wc, bc, out);
}

// round 6
// speedup vs baseline: 4.9021x; 1.8917x over previous
#include <cuda_runtime.h>
#include <math.h>

#define NQ       12
#define NPATCH   196
#define BATCH    4
#define NROWS    784        // BATCH * NPATCH
#define FEATDIM  2352       // NPATCH * NQ
#define FULLMASK 0xffffffffu

typedef unsigned long long u64;

// ---------------- device scratch (no allocations allowed) ----------------
__device__ float g_feats[NROWS * NQ];
__device__ float g_qkv[3 * NROWS * NQ];
__device__ float g_attn_out[NROWS * NQ];
__device__ float g_gcoef[3][80];      // per s: 40 gates x (0.5*cos2t, 0.5*sin2t)

// ---------------- packed f32x2 helpers (Blackwell) ----------------
__device__ __forceinline__ u64 pk2(float lo, float hi) {
    u64 r;
    asm("mov.b64 %0, {%1, %2};" : "=l"(r) : "r"(__float_as_uint(lo)), "r"(__float_as_uint(hi)));
    return r;
}
__device__ __forceinline__ void upk2(float& lo, float& hi, u64 v) {
    unsigned a, b;
    asm("mov.b64 {%0, %1}, %2;" : "=r"(a), "=r"(b) : "l"(v));
    lo = __uint_as_float(a); hi = __uint_as_float(b);
}
__device__ __forceinline__ u64 add2_(u64 a, u64 b) {
    u64 r; asm("add.rn.f32x2 %0, %1, %2;" : "=l"(r) : "l"(a), "l"(b)); return r;
}
__device__ __forceinline__ u64 mul2_(u64 a, u64 b) {
    u64 r; asm("mul.rn.f32x2 %0, %1, %2;" : "=l"(r) : "l"(a), "l"(b)); return r;
}
__device__ __forceinline__ u64 fma2_(u64 a, u64 b, u64 c) {
    u64 r; asm("fma.rn.f32x2 %0, %1, %2, %3;" : "=l"(r) : "l"(a), "l"(b), "l"(c)); return r;
}
__device__ __forceinline__ u64 shfl2(u64 v, int msk) {
    unsigned a, b;
    asm("mov.b64 {%0, %1}, %2;" : "=r"(a), "=r"(b) : "l"(v));
    a = __shfl_xor_sync(FULLMASK, a, msk);
    b = __shfl_xor_sync(FULLMASK, b, msk);
    u64 r;
    asm("mov.b64 %0, {%1, %2};" : "=l"(r) : "r"(a), "r"(b));
    return r;
}

// ---------------- Kernel A: channel-mean + patchify + projection ----------------
__global__ void proj_kernel(const float* __restrict__ x,
                            const float* __restrict__ Wp,
                            const float* __restrict__ bp) {
    int blk = blockIdx.x;                 // 0..783 = b*196 + p
    int b = blk / NPATCH, p = blk % NPATCH;
    int py = p / 14, px = p % 14;
    int j = threadIdx.x;                  // 0..255 patch element
    int r = j >> 4, c = j & 15;
    int h = py * 16 + r, w = px * 16 + c;
    long base = (long)b * 3 * 224 * 224 + (long)h * 224 + w;
    float v = (x[base] + x[base + 224 * 224] + x[base + 2 * 224 * 224]) * (1.0f / 3.0f);

    float acc[NQ];
#pragma unroll
    for (int k = 0; k < NQ; k++) acc[k] = v * Wp[k * 256 + j];

#pragma unroll
    for (int k = 0; k < NQ; k++) {
#pragma unroll
        for (int off = 16; off; off >>= 1)
            acc[k] += __shfl_down_sync(FULLMASK, acc[k], off);
    }
    __shared__ float sred[8][NQ];
    int warp = j >> 5, lane = j & 31;
    if (lane == 0) {
#pragma unroll
        for (int k = 0; k < NQ; k++) sred[warp][k] = acc[k];
    }
    __syncthreads();
    if (j < NQ) {
        float s = 0.f;
#pragma unroll
        for (int w8 = 0; w8 < 8; w8++) s += sred[w8][j];
        g_feats[blk * NQ + j] = s + bp[j];
    }
}

// ---------------- coefficient prep: 0.5*cos(2t), 0.5*sin(2t) per gate ----------------
__global__ void coef_kernel(const float* __restrict__ qp,
                            const float* __restrict__ kp,
                            const float* __restrict__ vp) {
    int t = threadIdx.x;                  // need 120
    if (t < 120) {
        int s = t / 40, gg = t % 40;
        const float* pp = (s == 0) ? qp : (s == 1) ? kp : vp;
        int l = gg / 20, g = gg % 20;
        float th = pp[l * 32 + g];        // pidx == gate index within layer
        float s2, c2; sincosf(2.0f * th, &s2, &c2);
        g_gcoef[s][2 * gg + 0] = 0.5f * c2;
        g_gcoef[s][2 * gg + 1] = 0.5f * s2;
    }
}

// ---------------- quantum gate primitives (packed warp-register state) ----------------
// Scalar amp index i = (lane << 7) | (k << 1) | h.
//   packed bit h      <-> qubit 11
//   A-reg bits 0..5   <-> qubits {8, 7, 4, 3, 2, 1}
//   lane bits 0..4    <-> qubits {10, 9, 6, 5, 0}
// ch = 0.5*cos2t, sh = 0.5*sin2t everywhere. neg1 = packed (-1,-1).

// w1-bit in lane (LBIT), w2-bit in A-regs (MLA); packed bit untouched
template<int LBIT, int MLA>
__device__ __forceinline__ void gM(u64* A, u64 ch2, u64 sgnsh2, u64 half2, u64 neg1) {
    const int msk = 1 << LBIT;
#pragma unroll
    for (int k = 0; k < 64; k++) {
        if ((k & MLA) == 0) {
            u64 s  = add2_(A[k], A[k | MLA]);
            u64 d  = fma2_(A[k | MLA], neg1, A[k]);
            u64 od = shfl2(d, msk);
            u64 h  = fma2_(sgnsh2, od, mul2_(ch2, d));
            u64 sv = mul2_(half2, s);
            A[k]       = add2_(sv, h);
            A[k | MLA] = fma2_(h, neg1, sv);
        }
    }
}

// w1-bit in lane (LBIT), w2-bit = packed bit
template<int LBIT>
__device__ __forceinline__ void gMp(u64* A, float ch, float sgnsh) {
    const int msk = 1 << LBIT;
#pragma unroll
    for (int k = 0; k < 64; k++) {
        float x0, x1; upk2(x0, x1, A[k]);
        float s = x0 + x1, d = x0 - x1;
        float od = __shfl_xor_sync(FULLMASK, d, msk);
        float h = fmaf(ch, d, sgnsh * od);
        float sv = 0.5f * s;
        A[k] = pk2(sv + h, sv - h);
    }
}

// w2-bit in lane (LBIT), w1-bit in A-regs (MHA); branch-free
template<int LBIT, int MHA>
__device__ __forceinline__ void gMlo(u64* A, u64 ch2, u64 sh2, u64 nsh2, u64 half2, u64 neg1) {
    const int msk = 1 << LBIT;
#pragma unroll
    for (int k = 0; k < 64; k++) {
        if ((k & MHA) == 0) {
            u64 x0 = A[k], x1 = A[k | MHA];
            u64 y0 = shfl2(x0, msk);
            u64 y1 = shfl2(x1, msk);
            u64 dx = fma2_(y0, neg1, x0);
            u64 dq = fma2_(y1, neg1, x1);
            u64 uh = mul2_(half2, add2_(x0, y0));
            u64 ph = mul2_(half2, add2_(x1, y1));
            A[k]       = fma2_(nsh2, dq, fma2_(ch2, dx, uh));
            A[k | MHA] = fma2_(ch2, dq, fma2_(sh2, dx, ph));
        }
    }
}

// both bits in A-regs (MHA = w1, MLA = w2)
template<int MHA, int MLA>
__device__ __forceinline__ void gR(u64* A, u64 ch2, u64 sh2, u64 nsh2, u64 half2, u64 neg1) {
#pragma unroll
    for (int k = 0; k < 64; k++) {
        if ((k & (MHA | MLA)) == 0) {
            u64 e00 = A[k], e01 = A[k | MLA], e10 = A[k | MHA], e11 = A[k | MHA | MLA];
            u64 u = add2_(e00, e01), v = fma2_(e01, neg1, e00);
            u64 p = add2_(e10, e11), q = fma2_(e11, neg1, e10);
            u64 hv = fma2_(nsh2, q, mul2_(ch2, v));
            u64 hq = fma2_(ch2, q, mul2_(sh2, v));
            u64 uh = mul2_(half2, u), ph = mul2_(half2, p);
            A[k]             = add2_(uh, hv);
            A[k | MLA]       = fma2_(hv, neg1, uh);
            A[k | MHA]       = add2_(ph, hq);
            A[k | MHA | MLA] = fma2_(hq, neg1, ph);
        }
    }
}

// w1-bit in A-regs (MHA), w2-bit = packed bit
template<int MHA>
__device__ __forceinline__ void gRp(u64* A, float ch, float sh) {
#pragma unroll
    for (int k = 0; k < 64; k++) {
        if ((k & MHA) == 0) {
            float e00, e01, e10, e11;
            upk2(e00, e01, A[k]);
            upk2(e10, e11, A[k | MHA]);
            float u = e00 + e01, v = e00 - e01;
            float p = e10 + e11, q = e10 - e11;
            float hv = fmaf(ch, v, -sh * q);
            float hq = fmaf(sh, v,  ch * q);
            float uh = 0.5f * u, ph = 0.5f * p;
            A[k]       = pk2(uh + hv, uh - hv);
            A[k | MHA] = pk2(ph + hq, ph - hq);
        }
    }
}

// ---------------- Kernel B: warp-per-state quantum evolution ----------------
__global__ void __launch_bounds__(128, 2) quantum_kernel() {
    int warp = threadIdx.x >> 5, lane = threadIdx.x & 31;
    int unit = blockIdx.x * 4 + warp;       // 0..2351
    int row = unit % NROWS;
    int s = unit / NROWS;                   // 0..2

    __shared__ float shco[4][80];
    {
        const float* gc = g_gcoef[s];
        for (int i = lane; i < 80; i += 32) shco[warp][i] = gc[i];
        __syncwarp();
    }
    const float* co = shco[warp];

    const u64 half2 = pk2(0.5f, 0.5f);
    const u64 neg1  = pk2(-1.0f, -1.0f);

    // angle encoding: lane q<12 computes cos/sin(x_q/2), broadcast via shfl
    float ang = (lane < NQ) ? 0.5f * g_feats[row * NQ + lane] : 0.0f;
    float cv, sv; sincosf(ang, &sv, &cv);

    // phi over lane bits: lane bit b -> qubit {10,9,6,5,0}
    float phi = 1.0f;
    {
        float cb, sb;
        cb = __shfl_sync(FULLMASK, cv, 10); sb = __shfl_sync(FULLMASK, sv, 10);
        phi *= (lane & 1)  ? sb : cb;
        cb = __shfl_sync(FULLMASK, cv, 9);  sb = __shfl_sync(FULLMASK, sv, 9);
        phi *= (lane & 2)  ? sb : cb;
        cb = __shfl_sync(FULLMASK, cv, 6);  sb = __shfl_sync(FULLMASK, sv, 6);
        phi *= (lane & 4)  ? sb : cb;
        cb = __shfl_sync(FULLMASK, cv, 5);  sb = __shfl_sync(FULLMASK, sv, 5);
        phi *= (lane & 8)  ? sb : cb;
        cb = __shfl_sync(FULLMASK, cv, 0);  sb = __shfl_sync(FULLMASK, sv, 0);
        phi *= (lane & 16) ? sb : cb;
    }

    // product-state init: packed bit -> qubit 11; A-bits 0..5 -> {8,7,4,3,2,1}
    u64 A[64];
    {
        float c11 = __shfl_sync(FULLMASK, cv, 11);
        float s11 = __shfl_sync(FULLMASK, sv, 11);
        A[0] = pk2(phi * c11, phi * s11);
        const int rq6[6] = {8, 7, 4, 3, 2, 1};
#pragma unroll
        for (int m = 0; m < 6; m++) {
            float cm = __shfl_sync(FULLMASK, cv, rq6[m]);
            float sm = __shfl_sync(FULLMASK, sv, rq6[m]);
            u64 cm2 = pk2(cm, cm), sm2 = pk2(sm, sm);
            int len = 1 << m;
#pragma unroll
            for (int i = 0; i < 64; i++) {
                if (i < len) {
                    A[i + len] = mul2_(A[i], sm2);
                    A[i] = mul2_(A[i], cm2);
                }
            }
        }
    }

    // 2 layers x 20 gates
#pragma unroll 1
    for (int l = 0; l < 2; l++) {
        const float* c = co + l * 40;
        float ch, sh; u64 ch2, sh2, nsh2;
#define LDC(g) ch = c[2*(g)]; sh = c[2*(g)+1]; ch2 = pk2(ch, ch); sh2 = pk2(sh, sh); nsh2 = pk2(-sh, -sh);
        LDC(0);  gM<4, 32>(A, ch2, (lane & 16) ? sh2 : nsh2, half2, neg1);  // (q0,q1)
        LDC(1);  gR<16, 8>(A, ch2, sh2, nsh2, half2, neg1);                 // (q2,q3)
        LDC(2);  gMlo<3, 4>(A, ch2, sh2, nsh2, half2, neg1);                // (q4,q5)
        LDC(3);  gM<2, 2>(A, ch2, (lane & 4) ? sh2 : nsh2, half2, neg1);    // (q6,q7)
        LDC(4);  gMlo<1, 1>(A, ch2, sh2, nsh2, half2, neg1);                // (q8,q9)
        LDC(5);  gMp<0>(A, ch, (lane & 1) ? sh : -sh);                      // (q10,q11)
        LDC(6);  gM<4, 16>(A, ch2, (lane & 16) ? sh2 : nsh2, half2, neg1);  // (q0,q2)
        LDC(7);  gR<32, 8>(A, ch2, sh2, nsh2, half2, neg1);                 // (q1,q3)
        LDC(8);  gMlo<2, 4>(A, ch2, sh2, nsh2, half2, neg1);                // (q4,q6)
        LDC(9);  gM<3, 2>(A, ch2, (lane & 8) ? sh2 : nsh2, half2, neg1);    // (q5,q7)
        LDC(10); gMlo<0, 1>(A, ch2, sh2, nsh2, half2, neg1);                // (q8,q10)
        LDC(11); gMp<1>(A, ch, (lane & 2) ? sh : -sh);                      // (q9,q11)
        LDC(12); gM<4, 4>(A, ch2, (lane & 16) ? sh2 : nsh2, half2, neg1);   // (q0,q4)
        LDC(13); gMlo<3, 32>(A, ch2, sh2, nsh2, half2, neg1);               // (q1,q5)
        LDC(14); gMlo<2, 16>(A, ch2, sh2, nsh2, half2, neg1);               // (q2,q6)
        LDC(15); gR<8, 2>(A, ch2, sh2, nsh2, half2, neg1);                  // (q3,q7)
        LDC(16); gM<4, 1>(A, ch2, (lane & 16) ? sh2 : nsh2, half2, neg1);   // (q0,q8)
        LDC(17); gMlo<1, 32>(A, ch2, sh2, nsh2, half2, neg1);               // (q1,q9)
        LDC(18); gMlo<0, 16>(A, ch2, sh2, nsh2, half2, neg1);               // (q2,q10)
        LDC(19); gRp<8>(A, ch, sh);                                         // (q3,q11)
#undef LDC
    }

    // expvals: squares; packed bit fold gives <Z_11>; then fold A-bits
    float D11 = 0.0f;
    float bb[64];
#pragma unroll
    for (int k = 0; k < 64; k++) {
        float x0, x1; upk2(x0, x1, A[k]);
        float s0 = x0 * x0, s1 = x1 * x1;
        D11 += s0 - s1;
        bb[k] = s0 + s1;
    }
    float D[6];
#pragma unroll
    for (int m = 0; m < 6; m++) {
        int half = 64 >> (m + 1);
        float dsum = 0.0f;
#pragma unroll
        for (int i = 0; i < 32; i++) {
            if (i < half) {
                float lo = bb[2 * i], hi = bb[2 * i + 1];
                dsum += lo - hi;
                bb[i] = lo + hi;
            }
        }
        D[m] = dsum;
    }
    float S = bb[0];                         // per-lane total prob

    // reduce D over lanes
#pragma unroll
    for (int b = 0; b < 5; b++)
        D11 += __shfl_xor_sync(FULLMASK, D11, 1 << b);
#pragma unroll
    for (int m = 0; m < 6; m++) {
#pragma unroll
        for (int b = 0; b < 5; b++)
            D[m] += __shfl_xor_sync(FULLMASK, D[m], 1 << b);
    }

    // lane-bit qubits: signed reductions of S
    float L[5];
#pragma unroll
    for (int b = 0; b < 5; b++) {
        float o = __shfl_xor_sync(FULLMASK, S, 1 << b);
        L[b] = (lane & (1 << b)) ? (o - S) : (S - o);
        S += o;
    }
#pragma unroll
    for (int b = 0; b < 5; b++) {
#pragma unroll
        for (int b2 = b + 1; b2 < 5; b2++)
            L[b] += __shfl_xor_sync(FULLMASK, L[b], 1 << b2);
    }

    if (lane == 0) {
        float* dst = g_qkv + ((long)s * NROWS + row) * NQ;
        dst[11] = D11;
        dst[8] = D[0]; dst[7] = D[1]; dst[4] = D[2];
        dst[3] = D[3]; dst[2] = D[4]; dst[1] = D[5];
        dst[10] = L[0]; dst[9] = L[1]; dst[6] = L[2]; dst[5] = L[3]; dst[0] = L[4];
    }
}

// ---------------- Kernel C: attention, warp per query row ----------------
__global__ void attn_kernel() {
    int gw = blockIdx.x * 4 + (threadIdx.x >> 5);    // 0..783
    int lane = threadIdx.x & 31;
    int b = gw / NPATCH, q = gw % NPATCH;
    const float scale = 0.28867513459481287f;        // 1/sqrt(12)

    const float* Qr = g_qkv + ((long)0 * NROWS + b * NPATCH + q) * NQ;
    const float* Kb = g_qkv + ((long)1 * NROWS + b * NPATCH) * NQ;
    const float* Vb = g_qkv + ((long)2 * NROWS + b * NPATCH) * NQ;

    float4 q0 = *(const float4*)(Qr);
    float4 q1 = *(const float4*)(Qr + 4);
    float4 q2 = *(const float4*)(Qr + 8);

    float sc[7];
    float m = -1e30f;
#pragma unroll
    for (int i = 0; i < 7; i++) {
        int k = lane + 32 * i;
        float v = -1e30f;
        if (k < NPATCH) {
            const float* Kr = Kb + k * NQ;
            float4 k0 = *(const float4*)Kr;
            float4 k1 = *(const float4*)(Kr + 4);
            float4 k2 = *(const float4*)(Kr + 8);
            v = q0.x * k0.x + q0.y * k0.y + q0.z * k0.z + q0.w * k0.w
              + q1.x * k1.x + q1.y * k1.y + q1.z * k1.z + q1.w * k1.w
              + q2.x * k2.x + q2.y * k2.y + q2.z * k2.z + q2.w * k2.w;
            v *= scale;
        }
        sc[i] = v;
        m = fmaxf(m, v);
    }
#pragma unroll
    for (int off = 16; off; off >>= 1)
        m = fmaxf(m, __shfl_xor_sync(FULLMASK, m, off));

    float den = 0.f;
    float o[NQ];
#pragma unroll
    for (int d = 0; d < NQ; d++) o[d] = 0.f;
#pragma unroll
    for (int i = 0; i < 7; i++) {
        int k = lane + 32 * i;
        if (k < NPATCH) {
            float e = __expf(sc[i] - m);
            den += e;
            const float* Vr = Vb + k * NQ;
            float4 v0 = *(const float4*)Vr;
            float4 v1 = *(const float4*)(Vr + 4);
            float4 v2 = *(const float4*)(Vr + 8);
            o[0] += e * v0.x; o[1] += e * v0.y; o[2]  += e * v0.z; o[3]  += e * v0.w;
            o[4] += e * v1.x; o[5] += e * v1.y; o[6]  += e * v1.z; o[7]  += e * v1.w;
            o[8] += e * v2.x; o[9] += e * v2.y; o[10] += e * v2.z; o[11] += e * v2.w;
        }
    }
#pragma unroll
    for (int off = 16; off; off >>= 1) {
        den += __shfl_xor_sync(FULLMASK, den, off);
#pragma unroll
        for (int d = 0; d < NQ; d++)
            o[d] += __shfl_xor_sync(FULLMASK, o[d], off);
    }
    if (lane == 0) {
        float inv = 1.0f / den;
        float* dst = g_attn_out + ((long)b * NPATCH + q) * NQ;
#pragma unroll
        for (int d = 0; d < NQ; d++) dst[d] = o[d] * inv;
    }
}

// ---------------- Kernel D: classifier (float4) ----------------
__global__ void cls_kernel(const float* __restrict__ Wc,
                           const float* __restrict__ bc,
                           float* __restrict__ out) {
    int o = blockIdx.x;                   // 0..999
    int t = threadIdx.x;                  // 256
    const float4* W4 = (const float4*)(Wc + (long)o * FEATDIM);
    const float4* A4 = (const float4*)g_attn_out;   // [4][588] float4
    float a0 = 0.f, a1 = 0.f, a2 = 0.f, a3 = 0.f;
    const int NF4 = FEATDIM / 4;          // 588
    for (int j = t; j < NF4; j += 256) {
        float4 w = W4[j];
        float4 x0 = A4[j];
        float4 x1 = A4[NF4 + j];
        float4 x2 = A4[2 * NF4 + j];
        float4 x3 = A4[3 * NF4 + j];
        a0 += w.x * x0.x + w.y * x0.y + w.z * x0.z + w.w * x0.w;
        a1 += w.x * x1.x + w.y * x1.y + w.z * x1.z + w.w * x1.w;
        a2 += w.x * x2.x + w.y * x2.y + w.z * x2.z + w.w * x2.w;
        a3 += w.x * x3.x + w.y * x3.y + w.z * x3.z + w.w * x3.w;
    }
#pragma unroll
    for (int off = 16; off; off >>= 1) {
        a0 += __shfl_down_sync(FULLMASK, a0, off);
        a1 += __shfl_down_sync(FULLMASK, a1, off);
        a2 += __shfl_down_sync(FULLMASK, a2, off);
        a3 += __shfl_down_sync(FULLMASK, a3, off);
    }
    __shared__ float sred[8][4];
    int warp = t >> 5, lane = t & 31;
    if (lane == 0) { sred[warp][0] = a0; sred[warp][1] = a1; sred[warp][2] = a2; sred[warp][3] = a3; }
    __syncthreads();
    if (t == 0) {
        float bias = bc[o];
        float r0 = 0.f, r1 = 0.f, r2 = 0.f, r3 = 0.f;
#pragma unroll
        for (int w8 = 0; w8 < 8; w8++) {
            r0 += sred[w8][0]; r1 += sred[w8][1]; r2 += sred[w8][2]; r3 += sred[w8][3];
        }
        out[0 * 1000 + o] = r0 + bias;
        out[1 * 1000 + o] = r1 + bias;
        out[2 * 1000 + o] = r2 + bias;
        out[3 * 1000 + o] = r3 + bias;
    }
}

// ---------------- launcher ----------------
extern "C" void kernel_launch(void* const* d_in, const int* in_sizes, int n_in,
                              void* d_out, int out_size) {
    const float* x  = (const float*)d_in[0];
    const float* Wp = (const float*)d_in[1];
    const float* bp = (const float*)d_in[2];
    const float* qp = (const float*)d_in[3];
    const float* kp = (const float*)d_in[4];
    const float* vp = (const float*)d_in[5];
    const float* Wc = (const float*)d_in[6];
    const float* bc = (const float*)d_in[7];
    float* out = (float*)d_out;

    coef_kernel<<<1, 128>>>(qp, kp, vp);
    proj_kernel<<<NROWS, 256>>>(x, Wp, bp);
    quantum_kernel<<<588, 128>>>();
    attn_kernel<<<196, 128>>>();
    cls_kernel<<<1000, 256>>>(Wc, bc, out);
}